// round 12
// baseline (speedup 1.0000x reference)
#include <cuda_runtime.h>
#include <math.h>

#define NB 4096
#define NK 1024
#define ND 128
#define NQ 2048
#define EPSV 1e-6f
#define SCALE 4294967296.0    // 2^32 fixed-point for deterministic final accum
#define FPS 65536.0f          // 2^16 fixed-point for warp-sum redux
#define CNT_SHIFT 50          // row-counter bits in the global accumulator

typedef unsigned long long u64;
typedef unsigned int u32;

// Scratch (device globals — no allocation allowed in kernel_launch)
__device__ u64    g_skey[ND * NK];     // sorted packed keys, layout [d][i]
__device__ u32    g_lutpair[ND * NQ];  // per-bucket start|end<<16 (fallback only)
__device__ uint4  g_rec[ND * NQ];      // 16B: kl_enc,k0_enc,k1_enc, idx+cnt pack
__device__ uint4  g_ext[ND];           // per-dim extremes: vmin,vmax,imin,imax
__device__ u64    g_accum;             // fixed-point sum + row counter (bits 50+)

// float -> order-preserving u32 (ascending)
__device__ __forceinline__ u32 enc_f32(float v) {
    u32 b = __float_as_uint(v);
    return (b & 0x80000000u) ? ~b : (b | 0x80000000u);
}
__device__ __forceinline__ float dec_f32(u32 u) {
    u32 b = (u & 0x80000000u) ? (u ^ 0x80000000u) : ~u;
    return __uint_as_float(b);
}

// Exactly monotone bucket map: fp add, mul by +const, float->int trunc are all
// monotone nondecreasing, so v1 <= v2 => bucket(v1) <= bucket(v2), and
// b1 < b2 => v1 < v2 (strict). Equal values map to equal buckets.
__device__ __forceinline__ int bucket_of(float v) {
    float f = (v + 6.0f) * ((float)NQ / 12.0f);
    f = fminf(fmaxf(f, 0.0f), (float)(NQ - 1));
    return (int)f;
}

// ---------------------------------------------------------------------------
// Kernel 1: per-column COUNTING sort of packed (value,index) u64 keys.
// 1024 threads, one element per thread. Fused lutpair + record emission.
// ---------------------------------------------------------------------------
__global__ void __launch_bounds__(1024) sort_columns_kernel(const float* __restrict__ cent) {
    __shared__ __align__(16) int s_hist[NQ];       // 8 KB
    __shared__ __align__(16) int s_pref[NQ + 4];   // 8 KB (exclusive prefix)
    __shared__ u64 s_tmp[NK];                      // 8 KB (arrival-order scatter)
    __shared__ u64 s_keys[NK];                     // 8 KB (final sorted)
    __shared__ int s_wsum[32];

    const int d = blockIdx.x;
    const int i = threadIdx.x;
    const int lane = i & 31, w = i >> 5;

    if (d == 0 && i == 0) g_accum = 0ULL;   // per-launch accumulator reset

    const float v = cent[i * ND + d];
    const u64 key = ((u64)enc_f32(v) << 32) | (u32)i;
    const int bkt = bucket_of(v);

    ((int2*)s_hist)[i] = make_int2(0, 0);   // NQ ints = 1024 int2
    __syncthreads();
    const int r = atomicAdd(&s_hist[bkt], 1);
    __syncthreads();

    // prefix sum over 2048 bins (2 per thread)
    const int2 c = ((const int2*)s_hist)[i];
    const int s = c.x + c.y;
    int incl = s;
#pragma unroll
    for (int off = 1; off < 32; off <<= 1) {
        int t = __shfl_up_sync(0xffffffffu, incl, off);
        if (lane >= off) incl += t;
    }
    if (lane == 31) s_wsum[w] = incl;
    __syncthreads();
    if (w == 0) {
        int ws = s_wsum[lane];
#pragma unroll
        for (int off = 1; off < 32; off <<= 1) {
            int t = __shfl_up_sync(0xffffffffu, ws, off);
            if (lane >= off) ws += t;
        }
        s_wsum[lane] = ws;
    }
    __syncthreads();
    {
        int p0 = (w > 0 ? s_wsum[w - 1] : 0) + (incl - s);
        ((int2*)s_pref)[i] = make_int2(p0, p0 + c.x);
    }
    if (i == 0) s_pref[NQ] = NK;
    __syncthreads();

    // scatter in arrival order
    const int st = s_pref[bkt];
    s_tmp[st + r] = key;
    __syncthreads();

    // parallel rank placement on unique full keys (deterministic)
    {
        const int cnt = s_hist[bkt];
        int rank = 0;
        for (int j = 0; j < cnt; j++) rank += (s_tmp[st + j] < key);
        s_keys[st + rank] = key;
    }
    __syncthreads();

    g_skey[d * NK + i] = s_keys[i];   // coalesced

    // lutpair + record: 2 buckets per thread, from smem-resident data
#pragma unroll
    for (int t = 0; t < 2; t++) {
        const int q = i + t * 1024;
        const int qs = s_pref[q], qe = s_pref[q + 1];
        g_lutpair[d * NQ + q] = (u32)qs | ((u32)qe << 16);
        const u64 kl = s_keys[max(qs - 1, 0)];
        const u64 k0 = s_keys[min(qs, NK - 1)];
        const u64 k1 = s_keys[min(qs + 1, NK - 1)];
        const u32 cc = (u32)min(qe - qs, 3);
        g_rec[d * NQ + q] = make_uint4(
            (u32)(kl >> 32), (u32)(k0 >> 32), (u32)(k1 >> 32),
            ((u32)kl & 1023u) | (((u32)k0 & 1023u) << 10) |
            (((u32)k1 & 1023u) << 20) | (cc << 30));
    }

    if (i == 0) {
        // min: first sorted key already has smallest index among min-ties.
        // max: first occurrence (smallest idx) = start of the max-value run.
        u32 umax = (u32)(s_keys[NK - 1] >> 32);
        int j = NK - 1;
        while (j > 0 && (u32)(s_keys[j - 1] >> 32) == umax) j--;
        g_ext[d] = make_uint4(
            __float_as_uint(dec_f32((u32)(s_keys[0] >> 32))),
            __float_as_uint(dec_f32(umax)),
            (u32)(s_keys[0] & 1023u),
            (u32)(s_keys[j] & 1023u));
    }
}

// ---------------------------------------------------------------------------
// Nearest-centroid resolve: one 16B record load resolves most queries
// (cnt<=1 or target<=k1); fallback loads lutpair + scans sorted keys.
// ---------------------------------------------------------------------------
__device__ __forceinline__ int resolve_near(const float xv, const int d) {
    const u32 te = enc_f32(xv);
    const int q = bucket_of(xv);
    const uint4 r = __ldg(&g_rec[d * NQ + q]);
    const u32 cc = r.w >> 30;

    u32 el, er, il, ir;
    if (cc == 0u || te <= r.y) {              // lower_bound = start
        el = r.x; il = r.w & 1023u;
        er = r.y; ir = (r.w >> 10) & 1023u;
    } else if (cc == 1u || te <= r.z) {       // lower_bound = start+1
        el = r.y; il = (r.w >> 10) & 1023u;
        er = r.z; ir = (r.w >> 20) & 1023u;
    } else {                                  // cnt>=2 and target beyond k1
        const u32 pr = __ldg(&g_lutpair[d * NQ + q]);
        const int st = (int)(pr & 0xffffu), en = (int)(pr >> 16);
        const int base = d * NK;
        const u64 target = ((u64)te) << 32;
        u64 prev = ((u64)r.z << 32) | ((r.w >> 20) & 1023u);
        u64 right = prev;
        bool found = false;
        for (int j = st + 2; j < en; j++) {
            u64 cur = __ldg(&g_skey[base + j]);
            if (cur >= target) { right = cur; found = true; break; }
            prev = cur;
        }
        if (!found) right = (en < NK) ? __ldg(&g_skey[base + en]) : prev;
        el = (u32)(prev >> 32);  il = (u32)prev & 1023u;
        er = (u32)(right >> 32); ir = (u32)right & 1023u;
    }

    const float vl = dec_f32(el), vr = dec_f32(er);
    float sl = xv - vl; sl *= sl;     // compare squares, like reference
    float sr = xv - vr; sr *= sr;
    return (sl < sr) ? (int)il : (sr < sl) ? (int)ir : min((int)il, (int)ir);
}

#define PAIR_BAR(id) asm volatile("bar.sync %0, 64;" :: "r"(id) : "memory")

// ---------------------------------------------------------------------------
// Kernel 2: TWO WARPS PER ROW (half-row each, 2 dims/thread), 2 rows per
// 128-thread block. Rows fully decoupled: per-row u16-packed histogram and
// 64-thread NAMED barriers (no block-wide __syncthreads). All warp
// reductions are single redux.sync instructions (max for mode keys; add on
// 2^16 fixed-point for distance sums — associative => deterministic).
// ---------------------------------------------------------------------------
__global__ void __launch_bounds__(ND) row_kernel(const float* __restrict__ x,
                                                 const float* __restrict__ cent,
                                                 float* __restrict__ out) {
    __shared__ u32 hist[2][NK];       // 8 KB: per row, near | far<<16
    __shared__ u32 s_keys[4][2];      // per-warp partial mode keys (N, F)
    __shared__ u32 s_part[4][3];      // per-warp fixed-point distance sums

    const int tid = threadIdx.x;
    const int warp = tid >> 5, lane = tid & 31;
    const int rowb = warp >> 1;          // row within block (0/1)
    const int half = warp & 1;           // which 64-dim half
    const int row = blockIdx.x * 2 + rowb;
    const int barid = 1 + rowb;
    const int ptid = (tid & 63);         // thread id within the pair

    // zero this row's hist: 256 uint4 / 64 threads = 4 each
    {
        uint4 z = make_uint4(0, 0, 0, 0);
        uint4* h = (uint4*)hist[rowb];
#pragma unroll
        for (int t = 0; t < 4; t++) h[ptid + 64 * t] = z;
    }

    // this thread's 2 dims: d0 = half*64 + lane*2
    const int dh = half * 32 + lane;                  // float2 index
    const int d0 = 2 * dh;
    const float2 xv = __ldg((const float2*)x + row * 64 + dh);

    const int n0 = resolve_near(xv.x, d0);
    const int n1 = resolve_near(xv.y, d0 + 1);

    // farthest: one of the column extremes (one LDG.128 per dim)
    int f0, f1;
    {
        const uint4 e0 = __ldg(&g_ext[d0]);
        const uint4 e1 = __ldg(&g_ext[d0 + 1]);
        float sm = xv.x - __uint_as_float(e0.x); sm *= sm;
        float sM = xv.x - __uint_as_float(e0.y); sM *= sM;
        f0 = (sm > sM) ? (int)e0.z : (sM > sm) ? (int)e0.w : min((int)e0.z, (int)e0.w);
        sm = xv.y - __uint_as_float(e1.x); sm *= sm;
        sM = xv.y - __uint_as_float(e1.y); sM *= sM;
        f1 = (sm > sM) ? (int)e1.z : (sM > sm) ? (int)e1.w : min((int)e1.z, (int)e1.w);
    }

    PAIR_BAR(barid);   // zeroing visible to the pair

    // histogram (u16 lanes: near low, far high; counts <= 128, no carry)
    u32 keyN, keyF;
    {
        u32 cn0 = ( atomicAdd(&hist[rowb][n0], 1u)       & 0xffffu) + 1u;
        u32 cn1 = ( atomicAdd(&hist[rowb][n1], 1u)       & 0xffffu) + 1u;
        u32 cf0 = ((atomicAdd(&hist[rowb][f0], 0x10000u) >> 16)   ) + 1u;
        u32 cf1 = ((atomicAdd(&hist[rowb][f1], 0x10000u) >> 16)   ) + 1u;
        keyN = max((cn0 << 10) | (1023u - (u32)n0), (cn1 << 10) | (1023u - (u32)n1));
        keyF = max((cf0 << 10) | (1023u - (u32)f0), (cf1 << 10) | (1023u - (u32)f1));
    }
    // single-instruction warp reductions; running-max mode trick composes:
    // the globally-last increment of a bin carries the final count.
    keyN = __reduce_max_sync(0xffffffffu, keyN);
    keyF = __reduce_max_sync(0xffffffffu, keyF);
    if (lane == 0) { s_keys[warp][0] = keyN; s_keys[warp][1] = keyF; }
    PAIR_BAR(barid);

    // combine the warp pair's partial keys -> row mode
    const int pw = warp ^ 1;
    const u32 kN = max(s_keys[warp][0], s_keys[pw][0]);
    const u32 kF = max(s_keys[warp][1], s_keys[pw][1]);
    const int mp = 1023 - (int)(kN & 1023u);
    const int mn = 1023 - (int)(kF & 1023u);

    // triplet terms (swap=True), eps added per element; partial over 64 dims
    const float2 pv = __ldg((const float2*)cent + mp * 64 + dh);
    const float2 nv = __ldg((const float2*)cent + mn * 64 + dh);
    float t0, t1, t2;
    {
        float a = xv.x - pv.x + EPSV;
        float b = xv.x - nv.x + EPSV;
        float c = pv.x - nv.x + EPSV;
        t0 = a * a; t1 = b * b; t2 = c * c;
        a = xv.y - pv.y + EPSV;
        b = xv.y - nv.y + EPSV;
        c = pv.y - nv.y + EPSV;
        t0 = fmaf(a, a, t0); t1 = fmaf(b, b, t1); t2 = fmaf(c, c, t2);
    }
    // 2^16 fixed-point warp sums: one redux each, associative (deterministic)
    u32 q0 = __reduce_add_sync(0xffffffffu, __float2uint_rn(t0 * FPS));
    u32 q1 = __reduce_add_sync(0xffffffffu, __float2uint_rn(t1 * FPS));
    u32 q2 = __reduce_add_sync(0xffffffffu, __float2uint_rn(t2 * FPS));
    if (lane == 0) { s_part[warp][0] = q0; s_part[warp][1] = q1; s_part[warp][2] = q2; }
    PAIR_BAR(barid);

    // one owner per row finishes the loss
    if (half == 0 && lane == 0) {
        float r0 = (float)(s_part[warp][0] + s_part[warp + 1][0]) * (1.0f / FPS);
        float r1 = (float)(s_part[warp][1] + s_part[warp + 1][1]) * (1.0f / FPS);
        float r2 = (float)(s_part[warp][2] + s_part[warp + 1][2]) * (1.0f / FPS);
        float dp = sqrtf(r0);
        float dn = fminf(sqrtf(r1), sqrtf(r2));
        float loss = fmaxf(dp - dn + 1.0f, 0.0f);

        // deterministic fixed-point accumulation with embedded row counter:
        // when the returned counter == NB-1, all other rows' sums are in.
        u64 fx = (u64)__double2ll_rn((double)loss * SCALE);
        u64 ret = atomicAdd(&g_accum, fx + (1ULL << CNT_SHIFT));
        if ((ret >> CNT_SHIFT) == (u64)(NB - 1)) {
            u64 total = (ret & ((1ULL << CNT_SHIFT) - 1)) + fx;
            out[0] = (float)((double)total * (1.0 / (4096.0 * SCALE)));
        }
    }
}

extern "C" void kernel_launch(void* const* d_in, const int* in_sizes, int n_in,
                              void* d_out, int out_size) {
    const float* input_features = (const float*)d_in[0];  // [4096, 128]
    const float* centroids      = (const float*)d_in[1];  // [1024, 128]
    float* out = (float*)d_out;

    sort_columns_kernel<<<ND, 1024>>>(centroids);
    row_kernel<<<NB / 2, ND>>>(input_features, centroids, out);
}

// round 13
// speedup vs baseline: 1.5047x; 1.5047x over previous
#include <cuda_runtime.h>
#include <math.h>

#define NB 4096
#define NK 1024
#define ND 128
#define NQ 2048
#define EPSV 1e-6f
#define SCALE 4294967296.0    // 2^32 fixed-point for deterministic final accum
#define FPS 65536.0f          // 2^16 fixed-point for warp-sum redux
#define CNT_SHIFT 50          // row-counter bits in the global accumulator

typedef unsigned long long u64;
typedef unsigned int u32;

// Scratch (device globals — no allocation allowed in kernel_launch)
__device__ u64    g_skey[ND * NK];     // sorted packed keys, layout [d][i]
__device__ u32    g_lutpair[ND * NQ];  // per-bucket start|end<<16 (fallback only)
__device__ uint4  g_rec[ND * NQ];      // 16B: kl_enc,k0_enc,k1_enc, idx+cnt pack
__device__ uint4  g_ext[ND];           // per-dim extremes: vmin,vmax,imin,imax
__device__ u64    g_accum;             // fixed-point sum + row counter (bits 50+)

// float -> order-preserving u32 (ascending)
__device__ __forceinline__ u32 enc_f32(float v) {
    u32 b = __float_as_uint(v);
    return (b & 0x80000000u) ? ~b : (b | 0x80000000u);
}
__device__ __forceinline__ float dec_f32(u32 u) {
    u32 b = (u & 0x80000000u) ? (u ^ 0x80000000u) : ~u;
    return __uint_as_float(b);
}

// Exactly monotone bucket map: fp add, mul by +const, float->int trunc are all
// monotone nondecreasing, so v1 <= v2 => bucket(v1) <= bucket(v2), and
// b1 < b2 => v1 < v2 (strict). Equal values map to equal buckets.
__device__ __forceinline__ int bucket_of(float v) {
    float f = (v + 6.0f) * ((float)NQ / 12.0f);
    f = fminf(fmaxf(f, 0.0f), (float)(NQ - 1));
    return (int)f;
}

// ---------------------------------------------------------------------------
// Kernel 1: per-column COUNTING sort of packed (value,index) u64 keys.
// 1024 threads, one element per thread. Fused lutpair + record emission.
// ---------------------------------------------------------------------------
__global__ void __launch_bounds__(1024) sort_columns_kernel(const float* __restrict__ cent) {
    __shared__ __align__(16) int s_hist[NQ];       // 8 KB
    __shared__ __align__(16) int s_pref[NQ + 4];   // 8 KB (exclusive prefix)
    __shared__ u64 s_tmp[NK];                      // 8 KB (arrival-order scatter)
    __shared__ u64 s_keys[NK];                     // 8 KB (final sorted)
    __shared__ int s_wsum[32];

    const int d = blockIdx.x;
    const int i = threadIdx.x;
    const int lane = i & 31, w = i >> 5;

    if (d == 0 && i == 0) g_accum = 0ULL;   // per-launch accumulator reset

    const float v = cent[i * ND + d];
    const u64 key = ((u64)enc_f32(v) << 32) | (u32)i;
    const int bkt = bucket_of(v);

    ((int2*)s_hist)[i] = make_int2(0, 0);   // NQ ints = 1024 int2
    __syncthreads();
    const int r = atomicAdd(&s_hist[bkt], 1);
    __syncthreads();

    // prefix sum over 2048 bins (2 per thread)
    const int2 c = ((const int2*)s_hist)[i];
    const int s = c.x + c.y;
    int incl = s;
#pragma unroll
    for (int off = 1; off < 32; off <<= 1) {
        int t = __shfl_up_sync(0xffffffffu, incl, off);
        if (lane >= off) incl += t;
    }
    if (lane == 31) s_wsum[w] = incl;
    __syncthreads();
    if (w == 0) {
        int ws = s_wsum[lane];
#pragma unroll
        for (int off = 1; off < 32; off <<= 1) {
            int t = __shfl_up_sync(0xffffffffu, ws, off);
            if (lane >= off) ws += t;
        }
        s_wsum[lane] = ws;
    }
    __syncthreads();
    {
        int p0 = (w > 0 ? s_wsum[w - 1] : 0) + (incl - s);
        ((int2*)s_pref)[i] = make_int2(p0, p0 + c.x);
    }
    if (i == 0) s_pref[NQ] = NK;
    __syncthreads();

    // scatter in arrival order
    const int st = s_pref[bkt];
    s_tmp[st + r] = key;
    __syncthreads();

    // parallel rank placement on unique full keys (deterministic)
    {
        const int cnt = s_hist[bkt];
        int rank = 0;
        for (int j = 0; j < cnt; j++) rank += (s_tmp[st + j] < key);
        s_keys[st + rank] = key;
    }
    __syncthreads();

    g_skey[d * NK + i] = s_keys[i];   // coalesced

    // lutpair + record: 2 buckets per thread, from smem-resident data
#pragma unroll
    for (int t = 0; t < 2; t++) {
        const int q = i + t * 1024;
        const int qs = s_pref[q], qe = s_pref[q + 1];
        g_lutpair[d * NQ + q] = (u32)qs | ((u32)qe << 16);
        const u64 kl = s_keys[max(qs - 1, 0)];
        const u64 k0 = s_keys[min(qs, NK - 1)];
        const u64 k1 = s_keys[min(qs + 1, NK - 1)];
        const u32 cc = (u32)min(qe - qs, 3);
        g_rec[d * NQ + q] = make_uint4(
            (u32)(kl >> 32), (u32)(k0 >> 32), (u32)(k1 >> 32),
            ((u32)kl & 1023u) | (((u32)k0 & 1023u) << 10) |
            (((u32)k1 & 1023u) << 20) | (cc << 30));
    }

    if (i == 0) {
        // min: first sorted key already has smallest index among min-ties.
        // max: first occurrence (smallest idx) = start of the max-value run.
        u32 umax = (u32)(s_keys[NK - 1] >> 32);
        int j = NK - 1;
        while (j > 0 && (u32)(s_keys[j - 1] >> 32) == umax) j--;
        g_ext[d] = make_uint4(
            __float_as_uint(dec_f32((u32)(s_keys[0] >> 32))),
            __float_as_uint(dec_f32(umax)),
            (u32)(s_keys[0] & 1023u),
            (u32)(s_keys[j] & 1023u));
    }
}

// ---------------------------------------------------------------------------
// Nearest-centroid resolve: one 16B record load resolves most queries
// (cnt<=1 or target<=k1); fallback loads lutpair + scans sorted keys.
// ---------------------------------------------------------------------------
__device__ __forceinline__ int resolve_near(const float xv, const int d) {
    const u32 te = enc_f32(xv);
    const int q = bucket_of(xv);
    const uint4 r = __ldg(&g_rec[d * NQ + q]);
    const u32 cc = r.w >> 30;

    u32 el, er, il, ir;
    if (cc == 0u || te <= r.y) {              // lower_bound = start
        el = r.x; il = r.w & 1023u;
        er = r.y; ir = (r.w >> 10) & 1023u;
    } else if (cc == 1u || te <= r.z) {       // lower_bound = start+1
        el = r.y; il = (r.w >> 10) & 1023u;
        er = r.z; ir = (r.w >> 20) & 1023u;
    } else {                                  // cnt>=2 and target beyond k1
        const u32 pr = __ldg(&g_lutpair[d * NQ + q]);
        const int st = (int)(pr & 0xffffu), en = (int)(pr >> 16);
        const int base = d * NK;
        const u64 target = ((u64)te) << 32;
        u64 prev = ((u64)r.z << 32) | ((r.w >> 20) & 1023u);
        u64 right = prev;
        bool found = false;
        for (int j = st + 2; j < en; j++) {
            u64 cur = __ldg(&g_skey[base + j]);
            if (cur >= target) { right = cur; found = true; break; }
            prev = cur;
        }
        if (!found) right = (en < NK) ? __ldg(&g_skey[base + en]) : prev;
        el = (u32)(prev >> 32);  il = (u32)prev & 1023u;
        er = (u32)(right >> 32); ir = (u32)right & 1023u;
    }

    const float vl = dec_f32(el), vr = dec_f32(er);
    float sl = xv - vl; sl *= sl;     // compare squares, like reference
    float sr = xv - vr; sr *= sr;
    return (sl < sr) ? (int)il : (sr < sl) ? (int)ir : min((int)il, (int)ir);
}

// ---------------------------------------------------------------------------
// Kernel 2: TWO WARPS PER ROW (half-row each, 2 dims/thread), 2 rows per
// 128-thread block. Block-wide __syncthreads ONLY (named barriers shrink the
// per-SM barrier pool and crater occupancy — r12 lesson). Warp reductions are
// single redux.sync instructions (max for mode keys; add on 2^16 fixed-point
// for distance sums — associative => deterministic).
// ---------------------------------------------------------------------------
__global__ void __launch_bounds__(ND) row_kernel(const float* __restrict__ x,
                                                 const float* __restrict__ cent,
                                                 float* __restrict__ out) {
    __shared__ u32 hist[2][NK];       // 8 KB: per row, near | far<<16
    __shared__ u32 s_keys[4][2];      // per-warp partial mode keys (N, F)
    __shared__ u32 s_part[4][3];      // per-warp fixed-point distance sums

    const int tid = threadIdx.x;
    const int warp = tid >> 5, lane = tid & 31;
    const int rowb = warp >> 1;          // row within block (0/1)
    const int half = warp & 1;           // which 64-dim half
    const int row = blockIdx.x * 2 + rowb;

    // zero both hist arrays: 512 uint4 / 128 threads = 4 each
    {
        uint4 z = make_uint4(0, 0, 0, 0);
        uint4* h = (uint4*)hist;
#pragma unroll
        for (int t = 0; t < 4; t++) h[tid + 128 * t] = z;
    }

    // this thread's 2 dims: d0 = half*64 + lane*2
    const int dh = half * 32 + lane;                  // float2 index
    const int d0 = 2 * dh;
    const float2 xv = __ldg((const float2*)x + row * 64 + dh);

    const int n0 = resolve_near(xv.x, d0);
    const int n1 = resolve_near(xv.y, d0 + 1);

    // farthest: one of the column extremes (one LDG.128 per dim)
    int f0, f1;
    {
        const uint4 e0 = __ldg(&g_ext[d0]);
        const uint4 e1 = __ldg(&g_ext[d0 + 1]);
        float sm = xv.x - __uint_as_float(e0.x); sm *= sm;
        float sM = xv.x - __uint_as_float(e0.y); sM *= sM;
        f0 = (sm > sM) ? (int)e0.z : (sM > sm) ? (int)e0.w : min((int)e0.z, (int)e0.w);
        sm = xv.y - __uint_as_float(e1.x); sm *= sm;
        sM = xv.y - __uint_as_float(e1.y); sM *= sM;
        f1 = (sm > sM) ? (int)e1.z : (sM > sm) ? (int)e1.w : min((int)e1.z, (int)e1.w);
    }

    __syncthreads();   // zeroing visible

    // histogram (u16 lanes: near low, far high; counts <= 128, no carry)
    u32 keyN, keyF;
    {
        u32 cn0 = ( atomicAdd(&hist[rowb][n0], 1u)       & 0xffffu) + 1u;
        u32 cn1 = ( atomicAdd(&hist[rowb][n1], 1u)       & 0xffffu) + 1u;
        u32 cf0 = ((atomicAdd(&hist[rowb][f0], 0x10000u) >> 16)   ) + 1u;
        u32 cf1 = ((atomicAdd(&hist[rowb][f1], 0x10000u) >> 16)   ) + 1u;
        keyN = max((cn0 << 10) | (1023u - (u32)n0), (cn1 << 10) | (1023u - (u32)n1));
        keyF = max((cf0 << 10) | (1023u - (u32)f0), (cf1 << 10) | (1023u - (u32)f1));
    }
    // single-instruction warp reductions; running-max mode trick composes:
    // the globally-last increment of a bin carries the final count.
    keyN = __reduce_max_sync(0xffffffffu, keyN);
    keyF = __reduce_max_sync(0xffffffffu, keyF);
    if (lane == 0) { s_keys[warp][0] = keyN; s_keys[warp][1] = keyF; }
    __syncthreads();

    // combine the warp pair's partial keys -> row mode
    const int pw = warp ^ 1;
    const u32 kN = max(s_keys[warp][0], s_keys[pw][0]);
    const u32 kF = max(s_keys[warp][1], s_keys[pw][1]);
    const int mp = 1023 - (int)(kN & 1023u);
    const int mn = 1023 - (int)(kF & 1023u);

    // triplet terms (swap=True), eps added per element; partial over 64 dims
    const float2 pv = __ldg((const float2*)cent + mp * 64 + dh);
    const float2 nv = __ldg((const float2*)cent + mn * 64 + dh);
    float t0, t1, t2;
    {
        float a = xv.x - pv.x + EPSV;
        float b = xv.x - nv.x + EPSV;
        float c = pv.x - nv.x + EPSV;
        t0 = a * a; t1 = b * b; t2 = c * c;
        a = xv.y - pv.y + EPSV;
        b = xv.y - nv.y + EPSV;
        c = pv.y - nv.y + EPSV;
        t0 = fmaf(a, a, t0); t1 = fmaf(b, b, t1); t2 = fmaf(c, c, t2);
    }
    // 2^16 fixed-point warp sums: one redux each, associative (deterministic)
    u32 q0 = __reduce_add_sync(0xffffffffu, __float2uint_rn(t0 * FPS));
    u32 q1 = __reduce_add_sync(0xffffffffu, __float2uint_rn(t1 * FPS));
    u32 q2 = __reduce_add_sync(0xffffffffu, __float2uint_rn(t2 * FPS));
    if (lane == 0) { s_part[warp][0] = q0; s_part[warp][1] = q1; s_part[warp][2] = q2; }
    __syncthreads();

    // one owner per row finishes the loss
    if (half == 0 && lane == 0) {
        float r0 = (float)(s_part[warp][0] + s_part[warp + 1][0]) * (1.0f / FPS);
        float r1 = (float)(s_part[warp][1] + s_part[warp + 1][1]) * (1.0f / FPS);
        float r2 = (float)(s_part[warp][2] + s_part[warp + 1][2]) * (1.0f / FPS);
        float dp = sqrtf(r0);
        float dn = fminf(sqrtf(r1), sqrtf(r2));
        float loss = fmaxf(dp - dn + 1.0f, 0.0f);

        // deterministic fixed-point accumulation with embedded row counter:
        // when the returned counter == NB-1, all other rows' sums are in.
        u64 fx = (u64)__double2ll_rn((double)loss * SCALE);
        u64 ret = atomicAdd(&g_accum, fx + (1ULL << CNT_SHIFT));
        if ((ret >> CNT_SHIFT) == (u64)(NB - 1)) {
            u64 total = (ret & ((1ULL << CNT_SHIFT) - 1)) + fx;
            out[0] = (float)((double)total * (1.0 / (4096.0 * SCALE)));
        }
    }
}

extern "C" void kernel_launch(void* const* d_in, const int* in_sizes, int n_in,
                              void* d_out, int out_size) {
    const float* input_features = (const float*)d_in[0];  // [4096, 128]
    const float* centroids      = (const float*)d_in[1];  // [1024, 128]
    float* out = (float*)d_out;

    sort_columns_kernel<<<ND, 1024>>>(centroids);
    row_kernel<<<NB / 2, ND>>>(input_features, centroids, out);
}